// round 8
// baseline (speedup 1.0000x reference)
#include <cuda_runtime.h>
#include <cuda_bf16.h>
#include <cuda_pipeline.h>
#include <math.h>

#define VOCAB 50000
#define D 256
#define Bn 128
#define Sn 64
#define Ln 32
#define Kn 32

// Scratch (device globals: allocation-free rule)
__device__ float  g_enc [Bn * Sn * D];          // enc_sents   (B,S,D)
__device__ float  g_encW[Bn * Sn * D];          // enc_sents@W (B,S,D)
__device__ float  g_keysV[Bn * Kn * D];         // keys@V      (B,K,D)
__device__ float  g_eK  [Bn * Sn * Kn];         // enc·keys    (B,S,K)
__device__ float2 g_Upk [(D / 2) * D];          // U packed: [p][c] = (U[2p][c], U[2p+1][c])

#define FMA_F32X2(d_, a_, b_, c_) \
    asm("fma.rn.f32x2 %0, %1, %2, %3;" : "=l"(d_) : "l"(a_), "l"(b_), "l"(c_))

// ---------------------------------------------------------------------------
// Fused: enc_sents[b,s,d] = sum_l emb[prgrph[b,s,l], d]
//        eK[b,s,k]        = sum_d enc[b,s,d] * keys[b,k,d]
// ---------------------------------------------------------------------------
__global__ void gather_eK_kernel(const int* __restrict__ prgrph,
                                 const float* __restrict__ emb,
                                 const float* __restrict__ keys) {
    __shared__ int   sidx[Ln];
    __shared__ float e_sh[D];
    int bs = blockIdx.x;
    int b  = bs / Sn;
    int t  = threadIdx.x;
    int w  = t >> 5, lane = t & 31;
    if (t < Ln) sidx[t] = prgrph[(size_t)bs * Ln + t];
    __syncthreads();
    float acc = 0.f;
#pragma unroll
    for (int l = 0; l < Ln; ++l) acc += __ldg(emb + (size_t)sidx[l] * D + t);
    g_enc[(size_t)bs * D + t] = acc;
    e_sh[t] = acc;
    __syncthreads();
#pragma unroll
    for (int r = 0; r < 4; ++r) {
        int k = w * 4 + r;
        const float* kr = keys + ((size_t)b * Kn + k) * D;
        float p = 0.f;
#pragma unroll
        for (int j = 0; j < 8; ++j) {
            int c = lane + 32 * j;
            p = fmaf(e_sh[c], __ldg(kr + c), p);
        }
#pragma unroll
        for (int o = 16; o > 0; o >>= 1) p += __shfl_xor_sync(0xffffffffu, p, o);
        if (lane == 0) g_eK[(size_t)bs * Kn + k] = p;
    }
}

// ---------------------------------------------------------------------------
__global__ void packU_kernel(const float* __restrict__ U) {
    int p = blockIdx.x;
    int c = threadIdx.x;
    g_Upk[p * D + c] = make_float2(U[(2 * p) * D + c], U[(2 * p + 1) * D + c]);
}

// ---------------------------------------------------------------------------
// 16-row GEMM tile: C[16,D] = A[16,D] @ Bm[D,D]
// ---------------------------------------------------------------------------
__device__ __forceinline__ void gemm16_body(const float* __restrict__ Ab,
                                            const float* __restrict__ Bm,
                                            float* __restrict__ Cb) {
    __shared__ float a_sh[16 * D];
    int t = threadIdx.x;
    for (int i = t; i < 16 * D; i += 256) a_sh[i] = Ab[i];
    __syncthreads();

    float acc[16];
#pragma unroll
    for (int k = 0; k < 16; ++k) acc[k] = 0.f;

    for (int d0 = 0; d0 < D; d0 += 8) {
        float u[8];
#pragma unroll
        for (int i = 0; i < 8; ++i) u[i] = __ldg(Bm + (size_t)(d0 + i) * D + t);
#pragma unroll
        for (int k = 0; k < 16; ++k) {
            float4 h1 = *(const float4*)&a_sh[k * D + d0];
            float4 h2 = *(const float4*)&a_sh[k * D + d0 + 4];
            acc[k] = fmaf(h1.x, u[0], acc[k]); acc[k] = fmaf(h1.y, u[1], acc[k]);
            acc[k] = fmaf(h1.z, u[2], acc[k]); acc[k] = fmaf(h1.w, u[3], acc[k]);
            acc[k] = fmaf(h2.x, u[4], acc[k]); acc[k] = fmaf(h2.y, u[5], acc[k]);
            acc[k] = fmaf(h2.z, u[6], acc[k]); acc[k] = fmaf(h2.w, u[7], acc[k]);
        }
    }
#pragma unroll
    for (int k = 0; k < 16; ++k) Cb[k * D + t] = acc[k];
}

// encW tiles (0..511) + keysV tiles (512..767)
__global__ void gemm_pre_kernel(const float* __restrict__ keys,
                                const float* __restrict__ V,
                                const float* __restrict__ W) {
    int blk = blockIdx.x;
    if (blk < 512) {
        size_t off = (size_t)blk * 16 * D;
        gemm16_body(g_enc + off, W, g_encW + off);
    } else {
        size_t off = (size_t)(blk - 512) * 16 * D;
        gemm16_body(keys + off, V, g_keysV + off);
    }
}

// ---------------------------------------------------------------------------
// The scan. One CTA per batch; 1024 threads (8 warps/SMSP for latency hiding).
// Thread t: cols (c0=t&127, c1=c0+128); row group g=t>>7 (8 groups) ->
//           rows kb=g*4 .. kb+3.
// Gate/norm: warp w <-> row w (32 warps, 32 rows).
// U streamed cyclically across steps via cp.async double buffering.
// h kept UNNORMALIZED in smem; rs_sh folded into gate/epilogue/output.
// ---------------------------------------------------------------------------
#define CHUNK_PAIRS 32
#define NCHUNK      4
#define CHUNK_BYTES (CHUNK_PAIRS * D * 8)   // 64 KB

__global__ void __launch_bounds__(1024, 1)
scan_kernel(const int* __restrict__ pmask,
            float* __restrict__ out) {
    extern __shared__ char smraw[];
    float* h       = (float*)smraw;                         // 32 KB
    char*  ubuf0   = smraw + Kn * D * 4;                    // 64 KB
    char*  ubuf1   = ubuf0 + CHUNK_BYTES;                   // 64 KB
    float* gate_sh = (float*)(ubuf1 + CHUNK_BYTES);         // 32
    float* rs_sh   = gate_sh + Kn;                          // 32
    float* np_sh   = rs_sh + Kn;                            // 32*4 partial sumsq
    int*   smask   = (int*)(np_sh + Kn * 4);                // 64

    const int b    = blockIdx.x;
    const int t    = threadIdx.x;
    const int c0   = t & 127;
    const int c1   = c0 + 128;
    const int g    = t >> 7;           // 0..7
    const int kb   = g * 4;            // rows kb..kb+3
    const int w    = t >> 5;           // 0..31
    const int wj   = w & 3;            // warp index within group
    const int lane = t & 31;

    float hrA[4], hrB[4], kvA[4], kvB[4];
#pragma unroll
    for (int r = 0; r < 4; ++r) {
        hrA[r] = 0.f; hrB[r] = 0.f;
        kvA[r] = g_keysV[((size_t)b * Kn + kb + r) * D + c0];
        kvB[r] = g_keysV[((size_t)b * Kn + kb + r) * D + c1];
    }
    for (int i = t; i < Kn * D; i += 1024) h[i] = 0.f;
    if (t < Sn) smask[t] = pmask[((size_t)b * Sn + t) * Ln];
    if (t < Kn) rs_sh[t] = 1.f;
    __syncthreads();

    const char* Usrc = (const char*)g_Upk;

    // initial prefetch of chunk 0 into ubuf0 (64KB / 1024 threads = 4 x 16B)
#pragma unroll
    for (int i = 0; i < 4; ++i) {
        size_t off = (size_t)t * 16 + (size_t)i * 1024 * 16;
        __pipeline_memcpy_async(ubuf0 + off, Usrc + off, 16);
    }
    __pipeline_commit();

    const size_t encRow = (size_t)b * Sn;

    for (int s = 0; s < Sn; ++s) {
        if (smask[s] == 0) continue;

        unsigned long long accA[4], accB[4];
#pragma unroll
        for (int r = 0; r < 4; ++r) { accA[r] = 0ull; accB[r] = 0ull; }

#pragma unroll
        for (int ch = 0; ch < NCHUNK; ++ch) {
            __pipeline_wait_prior(0);
            __syncthreads();                  // chunk ch resident; buffers safe
            {   // prefetch chunk (ch+1)&3 into the other buffer (cyclic)
                char* dst = (ch & 1) ? ubuf0 : ubuf1;
                const char* src = Usrc + (size_t)((ch + 1) & 3) * CHUNK_BYTES;
#pragma unroll
                for (int i = 0; i < 4; ++i) {
                    size_t off = (size_t)t * 16 + (size_t)i * 1024 * 16;
                    __pipeline_memcpy_async(dst + off, src + off, 16);
                }
                __pipeline_commit();
            }

            if (ch == 0) {
                // gate row w: sigmoid(rs*(e . h_raw[w]) + eK[w]); h still old
                const float* ep = g_enc + (encRow + s) * D;
                float p = 0.f;
#pragma unroll
                for (int j = 0; j < 8; ++j) {
                    float ev = __ldg(ep + lane + 32 * j);
                    p = fmaf(ev, h[w * D + lane + 32 * j], p);
                }
#pragma unroll
                for (int o = 16; o > 0; o >>= 1)
                    p += __shfl_xor_sync(0xffffffffu, p, o);
                if (lane == 0) {
                    float ek = __ldg(g_eK + (encRow + s) * Kn + w);
                    gate_sh[w] = 1.f / (1.f + expf(-(fmaf(rs_sh[w], p, ek))));
                }
            }

            const unsigned long long* usm =
                (const unsigned long long*)((ch & 1) ? ubuf1 : ubuf0);
            const int dbase = ch * (CHUNK_PAIRS * 2);

            for (int d0l = 0; d0l < CHUNK_PAIRS * 2; d0l += 8) {
                const int pl = d0l >> 1;
                unsigned long long ua0 = usm[(pl + 0) * D + c0];
                unsigned long long ub0 = usm[(pl + 0) * D + c1];
                unsigned long long ua1 = usm[(pl + 1) * D + c0];
                unsigned long long ub1 = usm[(pl + 1) * D + c1];
                unsigned long long ua2 = usm[(pl + 2) * D + c0];
                unsigned long long ub2 = usm[(pl + 2) * D + c1];
                unsigned long long ua3 = usm[(pl + 3) * D + c0];
                unsigned long long ub3 = usm[(pl + 3) * D + c1];
#pragma unroll
                for (int r = 0; r < 4; ++r) {
                    const ulonglong2* hp =
                        (const ulonglong2*)&h[(kb + r) * D + dbase + d0l];
                    ulonglong2 h01 = hp[0];
                    ulonglong2 h23 = hp[1];
                    FMA_F32X2(accA[r], h01.x, ua0, accA[r]);
                    FMA_F32X2(accB[r], h01.x, ub0, accB[r]);
                    FMA_F32X2(accA[r], h01.y, ua1, accA[r]);
                    FMA_F32X2(accB[r], h01.y, ub1, accB[r]);
                    FMA_F32X2(accA[r], h23.x, ua2, accA[r]);
                    FMA_F32X2(accB[r], h23.x, ub2, accB[r]);
                    FMA_F32X2(accA[r], h23.y, ua3, accA[r]);
                    FMA_F32X2(accB[r], h23.y, ub3, accB[r]);
                }
            }
        }
        __syncthreads();   // all h reads (gate + GEMM) complete; gate_sh visible

        // epilogue: new h (unnormalized) + register-based norm partials
        const float ewA = __ldg(g_encW + (encRow + s) * D + c0);
        const float ewB = __ldg(g_encW + (encRow + s) * D + c1);
        float np[4];
#pragma unroll
        for (int r = 0; r < 4; ++r) {
            int   k  = kb + r;
            float rs = rs_sh[k];
            float gt = gate_sh[k];
            float2 aA = *(float2*)&accA[r];
            float2 aB = *(float2*)&accB[r];
            float htA = fmaxf(fmaf(rs, aA.x + aA.y, kvA[r] + ewA), 0.f);
            float htB = fmaxf(fmaf(rs, aB.x + aB.y, kvB[r] + ewB), 0.f);
            hrA[r] = fmaf(gt, htA, rs * hrA[r]);
            hrB[r] = fmaf(gt, htB, rs * hrB[r]);
            h[k * D + c0] = hrA[r];
            h[k * D + c1] = hrB[r];
            np[r] = fmaf(hrA[r], hrA[r], hrB[r] * hrB[r]);
        }
#pragma unroll
        for (int o = 16; o > 0; o >>= 1)
#pragma unroll
            for (int r = 0; r < 4; ++r)
                np[r] += __shfl_xor_sync(0xffffffffu, np[r], o);
        if (lane == 0) {
#pragma unroll
            for (int r = 0; r < 4; ++r) np_sh[(kb + r) * 4 + wj] = np[r];
        }
        __syncthreads();   // np_sh ready; new h visible

        if (wj == 0 && lane < 4) {
            int k = kb + lane;
            float ssum = np_sh[k * 4 + 0] + np_sh[k * 4 + 1] +
                         np_sh[k * 4 + 2] + np_sh[k * 4 + 3];
            rs_sh[k] = rsqrtf(fmaxf(ssum, 1e-12f));
        }
        // rs_sh consumed next step after the chunk-0 __syncthreads (ordered),
        // and in the next epilogue after that chunk loop's barriers.
    }

    __syncthreads();   // final rs_sh visibility
#pragma unroll
    for (int r = 0; r < 4; ++r) {
        int k = kb + r;
        out[((size_t)b * Kn + k) * D + c0] = hrA[r] * rs_sh[k];
        out[((size_t)b * Kn + k) * D + c1] = hrB[r] * rs_sh[k];
    }
}

// ---------------------------------------------------------------------------
extern "C" void kernel_launch(void* const* d_in, const int* in_sizes, int n_in,
                              void* d_out, int out_size) {
    const int*   prgrph = (const int*)d_in[0];
    const int*   pmask  = (const int*)d_in[1];
    const float* keys   = (const float*)d_in[2];
    const float* emb    = (const float*)d_in[3];
    const float* U      = (const float*)d_in[4];
    const float* V      = (const float*)d_in[5];
    const float* W      = (const float*)d_in[6];
    float*       out    = (float*)d_out;

    const int scan_smem = Kn * D * 4 + 2 * CHUNK_BYTES +
                          (2 * Kn + Kn * 4) * 4 + Sn * 4 + 256;
    cudaFuncSetAttribute(scan_kernel, cudaFuncAttributeMaxDynamicSharedMemorySize,
                         scan_smem);

    gather_eK_kernel<<<Bn * Sn, 256>>>(prgrph, emb, keys);
    packU_kernel<<<D / 2, 256>>>(U);
    gemm_pre_kernel<<<768, 256>>>(keys, V, W);
    scan_kernel<<<Bn, 1024, scan_smem>>>(pmask, out);
}

// round 9
// speedup vs baseline: 1.2187x; 1.2187x over previous
#include <cuda_runtime.h>
#include <cuda_bf16.h>
#include <math.h>

#define VOCAB 50000
#define D 256
#define Bn 128
#define Sn 64
#define Ln 32
#define Kn 32

// Scratch (device globals: allocation-free rule)
__device__ float  g_enc [Bn * Sn * D];          // enc_sents   (B,S,D)
__device__ float  g_encW[Bn * Sn * D];          // enc_sents@W (B,S,D)
__device__ float  g_keysV[Bn * Kn * D];         // keys@V      (B,K,D)
__device__ float  g_eK  [Bn * Sn * Kn];         // enc·keys    (B,S,K)
__device__ float2 g_Upk [(D / 2) * D];          // U packed: [p][c] = (U[2p][c], U[2p+1][c])

#define FMA_F32X2(d_, a_, b_, c_) \
    asm("fma.rn.f32x2 %0, %1, %2, %3;" : "=l"(d_) : "l"(a_), "l"(b_), "l"(c_))

// ---------------------------------------------------------------------------
// Fused: enc_sents[b,s,d] = sum_l emb[prgrph[b,s,l], d]
//        eK[b,s,k]        = sum_d enc[b,s,d] * keys[b,k,d]
// ---------------------------------------------------------------------------
__global__ void gather_eK_kernel(const int* __restrict__ prgrph,
                                 const float* __restrict__ emb,
                                 const float* __restrict__ keys) {
    __shared__ int   sidx[Ln];
    __shared__ float e_sh[D];
    int bs = blockIdx.x;
    int b  = bs / Sn;
    int t  = threadIdx.x;
    int w  = t >> 5, lane = t & 31;
    if (t < Ln) sidx[t] = prgrph[(size_t)bs * Ln + t];
    __syncthreads();
    float acc = 0.f;
#pragma unroll
    for (int l = 0; l < Ln; ++l) acc += __ldg(emb + (size_t)sidx[l] * D + t);
    g_enc[(size_t)bs * D + t] = acc;
    e_sh[t] = acc;
    __syncthreads();
#pragma unroll
    for (int r = 0; r < 4; ++r) {
        int k = w * 4 + r;
        const float* kr = keys + ((size_t)b * Kn + k) * D;
        float p = 0.f;
#pragma unroll
        for (int j = 0; j < 8; ++j) {
            int c = lane + 32 * j;
            p = fmaf(e_sh[c], __ldg(kr + c), p);
        }
#pragma unroll
        for (int o = 16; o > 0; o >>= 1) p += __shfl_xor_sync(0xffffffffu, p, o);
        if (lane == 0) g_eK[(size_t)bs * Kn + k] = p;
    }
}

// ---------------------------------------------------------------------------
__global__ void packU_kernel(const float* __restrict__ U) {
    int p = blockIdx.x;
    int c = threadIdx.x;
    g_Upk[p * D + c] = make_float2(U[(2 * p) * D + c], U[(2 * p + 1) * D + c]);
}

// ---------------------------------------------------------------------------
// 16-row GEMM tile: C[16,D] = A[16,D] @ Bm[D,D]
// ---------------------------------------------------------------------------
__device__ __forceinline__ void gemm16_body(const float* __restrict__ Ab,
                                            const float* __restrict__ Bm,
                                            float* __restrict__ Cb) {
    __shared__ float a_sh[16 * D];
    int t = threadIdx.x;
    for (int i = t; i < 16 * D; i += 256) a_sh[i] = Ab[i];
    __syncthreads();

    float acc[16];
#pragma unroll
    for (int k = 0; k < 16; ++k) acc[k] = 0.f;

    for (int d0 = 0; d0 < D; d0 += 8) {
        float u[8];
#pragma unroll
        for (int i = 0; i < 8; ++i) u[i] = __ldg(Bm + (size_t)(d0 + i) * D + t);
#pragma unroll
        for (int k = 0; k < 16; ++k) {
            float4 h1 = *(const float4*)&a_sh[k * D + d0];
            float4 h2 = *(const float4*)&a_sh[k * D + d0 + 4];
            acc[k] = fmaf(h1.x, u[0], acc[k]); acc[k] = fmaf(h1.y, u[1], acc[k]);
            acc[k] = fmaf(h1.z, u[2], acc[k]); acc[k] = fmaf(h1.w, u[3], acc[k]);
            acc[k] = fmaf(h2.x, u[4], acc[k]); acc[k] = fmaf(h2.y, u[5], acc[k]);
            acc[k] = fmaf(h2.z, u[6], acc[k]); acc[k] = fmaf(h2.w, u[7], acc[k]);
        }
    }
#pragma unroll
    for (int k = 0; k < 16; ++k) Cb[k * D + t] = acc[k];
}

// encW tiles (0..511) + keysV tiles (512..767)
__global__ void gemm_pre_kernel(const float* __restrict__ keys,
                                const float* __restrict__ V,
                                const float* __restrict__ W) {
    int blk = blockIdx.x;
    if (blk < 512) {
        size_t off = (size_t)blk * 16 * D;
        gemm16_body(g_enc + off, W, g_encW + off);
    } else {
        size_t off = (size_t)(blk - 512) * 16 * D;
        gemm16_body(keys + off, V, g_keysV + off);
    }
}

// ---------------------------------------------------------------------------
// The scan. 256 CTAs = (batch, 16-row half); rows are fully independent, so
// halves never communicate. 256 threads/CTA, 2 CTAs/SM (17KB smem, 128 regs).
// Thread t: adjacent cols c0=2*(t&127), c1=c0+1; row group g=t>>7 ->
//           local rows kb=g*8 .. kb+7 (global rows half*16 + ...).
// U read straight from L2 via LDG.128 (both cols per load).
// h kept UNNORMALIZED in smem; rs_sh folded into gate/epilogue/output.
// ---------------------------------------------------------------------------
#define KH 16   // rows per CTA

__global__ void __launch_bounds__(256, 2)
scan_kernel(const int* __restrict__ pmask,
            float* __restrict__ out) {
    __shared__ float h[KH * D];          // 16 KB, unnormalized local rows
    __shared__ float gate_sh[KH];
    __shared__ float rs_sh[KH];
    __shared__ float np_sh[KH * 4];
    __shared__ int   smask[Sn];

    const int b    = blockIdx.x >> 1;
    const int half = blockIdx.x & 1;
    const int kgbl = half * KH;          // global row base of this CTA
    const int t    = threadIdx.x;
    const int cp   = t & 127;
    const int c0   = cp * 2;
    const int c1   = c0 + 1;
    const int g    = t >> 7;             // 0..1
    const int kb   = g * 8;              // local rows kb..kb+7
    const int w    = t >> 5;             // 0..7
    const int wj   = w & 3;
    const int lane = t & 31;

    // persistent registers: this thread's h values + loop-invariant keysV
    float hrA[8], hrB[8], kvA[8], kvB[8];
#pragma unroll
    for (int r = 0; r < 8; ++r) {
        hrA[r] = 0.f; hrB[r] = 0.f;
        float2 kv = __ldg((const float2*)
            (g_keysV + ((size_t)b * Kn + kgbl + kb + r) * D + c0));
        kvA[r] = kv.x; kvB[r] = kv.y;
    }
    for (int i = t; i < KH * D; i += 256) h[i] = 0.f;
    if (t < Sn) smask[t] = pmask[((size_t)b * Sn + t) * Ln];
    if (t < KH) rs_sh[t] = 1.f;
    __syncthreads();

    const ulonglong2* Upk2 = (const ulonglong2*)g_Upk;   // [p][cp] 16B units
    const size_t encRow = (size_t)b * Sn;

    for (int s = 0; s < Sn; ++s) {
        if (smask[s] == 0) continue;

        // ---- gate: warp w handles local rows 2w, 2w+1 (reads old h, rs) ----
        {
            const float* ep = g_enc + (encRow + s) * D;
            float ev[8];
#pragma unroll
            for (int j = 0; j < 8; ++j) ev[j] = __ldg(ep + lane + 32 * j);
#pragma unroll
            for (int r = 0; r < 2; ++r) {
                int k = 2 * w + r;
                float p = 0.f;
#pragma unroll
                for (int j = 0; j < 8; ++j)
                    p = fmaf(ev[j], h[k * D + lane + 32 * j], p);
#pragma unroll
                for (int o = 16; o > 0; o >>= 1)
                    p += __shfl_xor_sync(0xffffffffu, p, o);
                if (lane == 0) {
                    float ek = __ldg(g_eK + (encRow + s) * Kn + kgbl + k);
                    gate_sh[k] = 1.f / (1.f + expf(-(fmaf(rs_sh[k], p, ek))));
                }
            }
        }

        // ---- GEMM: acc = h_raw @ U for 8 local rows x 2 adjacent cols ----
        unsigned long long accA[8], accB[8];
#pragma unroll
        for (int r = 0; r < 8; ++r) { accA[r] = 0ull; accB[r] = 0ull; }

#pragma unroll 2
        for (int p4 = 0; p4 < D / 2; p4 += 4) {
            // one LDG.128 per pair covers both columns (c0, c1 adjacent)
            ulonglong2 u0 = __ldg(Upk2 + (size_t)(p4 + 0) * 128 + cp);
            ulonglong2 u1 = __ldg(Upk2 + (size_t)(p4 + 1) * 128 + cp);
            ulonglong2 u2 = __ldg(Upk2 + (size_t)(p4 + 2) * 128 + cp);
            ulonglong2 u3 = __ldg(Upk2 + (size_t)(p4 + 3) * 128 + cp);
#pragma unroll
            for (int r = 0; r < 8; ++r) {
                const ulonglong2* hp =
                    (const ulonglong2*)&h[(kb + r) * D + p4 * 2];
                ulonglong2 h01 = hp[0];   // pairs p4, p4+1
                ulonglong2 h23 = hp[1];   // pairs p4+2, p4+3
                FMA_F32X2(accA[r], h01.x, u0.x, accA[r]);
                FMA_F32X2(accB[r], h01.x, u0.y, accB[r]);
                FMA_F32X2(accA[r], h01.y, u1.x, accA[r]);
                FMA_F32X2(accB[r], h01.y, u1.y, accB[r]);
                FMA_F32X2(accA[r], h23.x, u2.x, accA[r]);
                FMA_F32X2(accB[r], h23.x, u2.y, accB[r]);
                FMA_F32X2(accA[r], h23.y, u3.x, accA[r]);
                FMA_F32X2(accB[r], h23.y, u3.y, accB[r]);
            }
        }
        __syncthreads();   // S1: all reads of old h done; gate_sh visible

        // ---- epilogue: new h (unnormalized) + register norm partials ----
        const float2 ew = __ldg((const float2*)(g_encW + (encRow + s) * D + c0));
        float np[8];
#pragma unroll
        for (int r = 0; r < 8; ++r) {
            int   k  = kb + r;
            float rs = rs_sh[k];
            float gt = gate_sh[k];
            float2 aA = *(float2*)&accA[r];
            float2 aB = *(float2*)&accB[r];
            float htA = fmaxf(fmaf(rs, aA.x + aA.y, kvA[r] + ew.x), 0.f);
            float htB = fmaxf(fmaf(rs, aB.x + aB.y, kvB[r] + ew.y), 0.f);
            hrA[r] = fmaf(gt, htA, rs * hrA[r]);
            hrB[r] = fmaf(gt, htB, rs * hrB[r]);
            *(float2*)&h[k * D + c0] = make_float2(hrA[r], hrB[r]);
            np[r] = fmaf(hrA[r], hrA[r], hrB[r] * hrB[r]);
        }
#pragma unroll
        for (int o = 16; o > 0; o >>= 1)
#pragma unroll
            for (int r = 0; r < 8; ++r)
                np[r] += __shfl_xor_sync(0xffffffffu, np[r], o);
        if (lane == 0) {
#pragma unroll
            for (int r = 0; r < 8; ++r) np_sh[(kb + r) * 4 + wj] = np[r];
        }
        __syncthreads();   // S2: np_sh ready, new h visible

        if (t < KH) {
            float ssum = np_sh[t * 4 + 0] + np_sh[t * 4 + 1] +
                         np_sh[t * 4 + 2] + np_sh[t * 4 + 3];
            rs_sh[t] = rsqrtf(fmaxf(ssum, 1e-12f));
        }
        __syncthreads();   // S3: rs visible for next gate / output
    }

#pragma unroll
    for (int r = 0; r < 8; ++r) {
        int k = kb + r;
        *(float2*)&out[((size_t)b * Kn + kgbl + k) * D + c0] =
            make_float2(hrA[r] * rs_sh[k], hrB[r] * rs_sh[k]);
    }
}

// ---------------------------------------------------------------------------
extern "C" void kernel_launch(void* const* d_in, const int* in_sizes, int n_in,
                              void* d_out, int out_size) {
    const int*   prgrph = (const int*)d_in[0];
    const int*   pmask  = (const int*)d_in[1];
    const float* keys   = (const float*)d_in[2];
    const float* emb    = (const float*)d_in[3];
    const float* U      = (const float*)d_in[4];
    const float* V      = (const float*)d_in[5];
    const float* W      = (const float*)d_in[6];
    float*       out    = (float*)d_out;

    gather_eK_kernel<<<Bn * Sn, 256>>>(prgrph, emb, keys);
    packU_kernel<<<D / 2, 256>>>(U);
    gemm_pre_kernel<<<768, 256>>>(keys, V, W);
    scan_kernel<<<Bn * 2, 256>>>(pmask, out);
}